// round 15
// baseline (speedup 1.0000x reference)
#include <cuda_runtime.h>
#include <cuda_fp16.h>
#include <cstdint>

#define DM   1024
#define NH   16
#define DK   64
#define BATCH 2
#define SEQ  2048
#define MROWS (BATCH*SEQ)   // 4096
#define NW   (DM*DM)
#define NX   (MROWS*DM)
#define NHD  (BATCH*NH*SEQ*DK)

// Scratch (sanctioned __device__ globals)
__device__ __half g_Wf[4*NW];    // fp16 weights (Wq,Wk,Wv,Wo)
__device__ __half g_Xf[3*NX];    // fp16 inputs
__device__ __half g_Cf[NX];      // fp16 ctx [b,s,h*d]
__device__ __half g_Qf[NHD];     // fp16 Q (prescaled) [b,h,s,d]
__device__ __half g_Kf[NHD];     // fp16 K [b,h,s,d]
__device__ __half g_Vf[NHD];     // fp16 V TRANSPOSED [b,h,d,s]

// ---------------------------------------------------------------------------
// helpers
// ---------------------------------------------------------------------------
__device__ __forceinline__ float ex2f(float x) {
    float y;
    asm("ex2.approx.f32 %0, %1;" : "=f"(y) : "f"(x));
    return y;
}
__device__ __forceinline__ uint32_t h2ex2(uint32_t x) {
    uint32_t y;
    asm("ex2.approx.f16x2 %0, %1;" : "=r"(y) : "r"(x));
    return y;
}
__device__ __forceinline__ uint32_t packh2(float lo, float hi) {
    uint32_t u;
    asm("cvt.rn.f16x2.f32 %0, %1, %2;" : "=r"(u) : "f"(hi), "f"(lo));
    return u;
}
__device__ __forceinline__ float2 h2unpack(uint32_t u) {
    __half2 h = *reinterpret_cast<__half2*>(&u);
    return __half22float2(h);
}
__device__ __forceinline__ void mma_fp16(float* c, const uint32_t* a,
                                         uint32_t b0, uint32_t b1) {
    asm volatile(
        "mma.sync.aligned.m16n8k16.row.col.f32.f16.f16.f32 "
        "{%0,%1,%2,%3},{%4,%5,%6,%7},{%8,%9},{%0,%1,%2,%3};"
        : "+f"(c[0]), "+f"(c[1]), "+f"(c[2]), "+f"(c[3])
        : "r"(a[0]), "r"(a[1]), "r"(a[2]), "r"(a[3]), "r"(b0), "r"(b1));
}
__device__ __forceinline__ void ldsm4(uint32_t* r, uint32_t addr) {
    asm volatile("ldmatrix.sync.aligned.m8n8.x4.shared.b16 {%0,%1,%2,%3}, [%4];"
        : "=r"(r[0]), "=r"(r[1]), "=r"(r[2]), "=r"(r[3]) : "r"(addr));
}
__device__ __forceinline__ void cpa16(uint32_t dst, const void* src) {
    asm volatile("cp.async.cg.shared.global [%0], [%1], 16;\n"
                 :: "r"(dst), "l"(src));
}
#define CP_COMMIT() asm volatile("cp.async.commit_group;\n" ::: "memory")
#define CP_WAIT1()  asm volatile("cp.async.wait_group 1;\n" ::: "memory")
#define CP_WAIT2()  asm volatile("cp.async.wait_group 2;\n" ::: "memory")

// ---------------------------------------------------------------------------
// prep: plain fp16 conversion. z 0-3 weights, z 4-6 inputs.
// ---------------------------------------------------------------------------
__global__ __launch_bounds__(256)
void prep(const float* __restrict__ Wq, const float* __restrict__ Wk,
          const float* __restrict__ Wv, const float* __restrict__ Wo,
          const float* __restrict__ Xq, const float* __restrict__ Xk,
          const float* __restrict__ Xv)
{
    const int z = blockIdx.z;
    const float* src = (z==0)?Wq:(z==1)?Wk:(z==2)?Wv:(z==3)?Wo:
                       (z==4)?Xq:(z==5)?Xk:Xv;
    __half* dst = (z < 4) ? (g_Wf + (size_t)z*NW) : (g_Xf + (size_t)(z-4)*NX);
    const int n4 = ((z < 4) ? NW : NX) >> 2;
    const int stride = gridDim.x * blockDim.x;
    for (int i = blockIdx.x*blockDim.x + threadIdx.x; i < n4; i += stride) {
        float4 v = ((const float4*)src)[i];
        uint2 u;
        u.x = packh2(v.x, v.y);
        u.y = packh2(v.z, v.w);
        *(uint2*)&dst[(size_t)i*4] = u;
    }
}

// ---------------------------------------------------------------------------
// GEMM on mma.sync fp16 m16n8k16 + ldmatrix, 4-stage cp.async pipeline.
// (unchanged from R13 champion)
// ---------------------------------------------------------------------------
#define PW2 20
#define S_A2 (128*PW2)                 // 2560 words A
#define STG2 (2*S_A2)                  // 5120 words per stage (A + W)
#define GEMM_SMEM_BYTES (4*STG2*4)     // 81920

__global__ __launch_bounds__(256, 2)
void gemm_fp16(int mode, const float* __restrict__ b0p,
               const float* __restrict__ b1p, const float* __restrict__ b2p,
               float* __restrict__ outp)
{
    extern __shared__ uint32_t gsm[];

    const int z = blockIdx.z;
    const __half* Af = mode ? (g_Xf + (size_t)z*NX) : g_Cf;
    const int wsel = mode ? z : 3;
    const __half* WG = g_Wf + (size_t)wsel*NW;
    const float* bias = mode ? ((z==0)?b0p:(z==1)?b1p:b2p) : b0p;

    const int m0 = blockIdx.y * 128;
    const int n0 = blockIdx.x * 128;
    const int tid = threadIdx.x;
    const int w = tid >> 5;
    const int lane = tid & 31;
    const int g = lane >> 2, tg = lane & 3;
    const int wm = w & 3;
    const int wn = w >> 2;

    const uint32_t sbase = (uint32_t)__cvta_generic_to_shared(gsm);

    const uint32_t aOffW = (uint32_t)((wm*32 + (lane&7) + ((lane>>3)&1)*8)*PW2
                                      + (lane>>4)*4);
    const uint32_t wOffW = (uint32_t)((wn*64 + ((lane>>4)&1)*8 + (lane&7))*PW2
                                      + ((lane>>3)&1)*4);

    auto stage = [&](int kc, int s) {
        int k0 = kc * 32;
        uint32_t bb = sbase + (uint32_t)(s * STG2) * 4u;
#pragma unroll
        for (int i = 0; i < 2; i++) {
            int f = tid + i*256;
            int r = f >> 2, ch = f & 3;
            cpa16(bb + (uint32_t)(r*PW2 + ch*4)*4u,
                  Af + (size_t)(m0 + r)*DM + k0 + ch*8);
        }
#pragma unroll
        for (int i = 0; i < 2; i++) {
            int f = tid + i*256;
            int r = f >> 2, ch = f & 3;
            cpa16(bb + S_A2*4u + (uint32_t)(r*PW2 + ch*4)*4u,
                  WG + (size_t)(n0 + r)*DM + k0 + ch*8);
        }
    };

    float acc[2][8][4];
#pragma unroll
    for (int mi = 0; mi < 2; mi++)
#pragma unroll
        for (int nt = 0; nt < 8; nt++)
#pragma unroll
            for (int j = 0; j < 4; j++) acc[mi][nt][j] = 0.f;

    stage(0, 0); CP_COMMIT();
    stage(1, 1); CP_COMMIT();
    stage(2, 2); CP_COMMIT();

    const int NCH = DM/32;   // 32 chunks
    for (int kc = 0; kc < NCH; kc++) {
        CP_WAIT2();
        __syncthreads();

        uint32_t bb = sbase + (uint32_t)((kc & 3) * STG2) * 4u;
        uint32_t aA = bb + aOffW*4u;
        uint32_t wB = bb + S_A2*4u + wOffW*4u;

#pragma unroll
        for (int ks = 0; ks < 2; ks++) {
            uint32_t off = (uint32_t)(ks*8)*4u;
            uint32_t af[2][4];
            ldsm4(af[0], aA + off);
            ldsm4(af[1], aA + (uint32_t)(16*PW2)*4u + off);
#pragma unroll
            for (int p = 0; p < 4; p++) {
                uint32_t wb[4];
                ldsm4(wb, wB + (uint32_t)(p*16*PW2)*4u + off);
#pragma unroll
                for (int q = 0; q < 2; q++) {
                    int nt = p*2 + q;
#pragma unroll
                    for (int mi = 0; mi < 2; mi++)
                        mma_fp16(acc[mi][nt], af[mi], wb[q*2], wb[q*2+1]);
                }
            }
        }

        if (kc + 3 < NCH) stage(kc + 3, (kc + 3) & 3);
        CP_COMMIT();
    }

    // epilogue
    const float QSCALE = 0.125f * 1.4426950408889634f;
#pragma unroll
    for (int nt = 0; nt < 8; nt++) {
        int ncl = wn*64 + nt*8 + 2*tg;
        int gn = n0 + ncl;
        float bb0 = bias[gn], bb1 = bias[gn + 1];
#pragma unroll
        for (int mi = 0; mi < 2; mi++) {
            int mA = m0 + wm*32 + mi*16 + g;
            int mB = mA + 8;
            float x0 = acc[mi][nt][0] + bb0, x1 = acc[mi][nt][1] + bb1;
            float y0 = acc[mi][nt][2] + bb0, y1 = acc[mi][nt][3] + bb1;
            if (mode) {
                int bA = mA >> 11, sA = mA & (SEQ-1);
                int sB = sA + 8;
                int h = gn >> 6, d = gn & 63;
                if (z == 2) {
                    size_t vb = ((size_t)(bA*NH + h)) * DK;
                    g_Vf[(vb + d  )*SEQ + sA] = __float2half_rn(x0);
                    g_Vf[(vb + d+1)*SEQ + sA] = __float2half_rn(x1);
                    g_Vf[(vb + d  )*SEQ + sB] = __float2half_rn(y0);
                    g_Vf[(vb + d+1)*SEQ + sB] = __float2half_rn(y1);
                } else {
                    __half* dst = (z == 0) ? g_Qf : g_Kf;
                    float sc = (z == 0) ? QSCALE : 1.0f;
                    size_t oA = (((size_t)(bA*NH + h)) * SEQ + sA) * DK + d;
                    size_t oB = (((size_t)(bA*NH + h)) * SEQ + sB) * DK + d;
                    *(uint32_t*)&dst[oA] = packh2(x0*sc, x1*sc);
                    *(uint32_t*)&dst[oB] = packh2(y0*sc, y1*sc);
                }
            } else {
                *(float2*)&outp[(size_t)mA * DM + gn] = make_float2(x0, x1);
                *(float2*)&outp[(size_t)mB * DM + gn] = make_float2(y0, y1);
            }
        }
    }
}

// ---------------------------------------------------------------------------
// Flash attention, fp16 m16n8k16 + ldmatrix, v3:
//  - q-tile 256 per block (two 128-row halves share each staged K/V tile)
//    -> grid 256 blocks = SINGLE WAVE (296 resident slots)
//  - triple-buffered K/V, ONE __syncthreads per tile; stage(t+2) issued
//    right after the barrier (freed buffer reader-free since last iter)
//  - P via ex2.approx.f16x2 directly in pa register layout
// smem: Qs 256x36 | Ks[3] 64x36 | Vs[3] 64x36 = 92160 B; 2 blocks/SM.
// ---------------------------------------------------------------------------
#define PW 36
#define AQ_SZ (256*PW)   // 9216 words
#define AK_SZ (64*PW)    // 2304 words
#define ATTN_SMEM_BYTES ((AQ_SZ + 6*AK_SZ)*4)   // 92160

__global__ __launch_bounds__(256, 2)
void attn_fp16()
{
    extern __shared__ uint32_t sm[];

    const int bh = blockIdx.y;
    const int q0 = blockIdx.x * 256;
    const size_t base = (size_t)bh * SEQ * DK;     // [b,h,s,d] Q/K
    const size_t vbase = (size_t)bh * DK * SEQ;    // [b,h,d,s] V
    const int tid = threadIdx.x;
    const int w = tid >> 5;
    const int lane = tid & 31;
    const int g = lane >> 2, tg = lane & 3;

    const uint32_t sbase = (uint32_t)__cvta_generic_to_shared(sm);

    // LDSM lane addressing (words); q offset per 128-row half
    uint32_t qOff[2];
#pragma unroll
    for (int hh = 0; hh < 2; hh++)
        qOff[hh] = (uint32_t)((hh*128 + w*16 + (lane&7) + ((lane>>3)&1)*8)*PW
                              + (lane>>4)*4);
    const uint32_t bOffW = (uint32_t)((((lane>>4)&1)*8 + (lane&7))*PW
                                      + ((lane>>3)&1)*4);

    auto stageKV = [&](int t, int b) {
        int s0 = t * 64;
        uint32_t kB = sbase + (uint32_t)(AQ_SZ + b*AK_SZ)*4u;
        uint32_t vB = sbase + (uint32_t)(AQ_SZ + (3 + b)*AK_SZ)*4u;
#pragma unroll
        for (int i = 0; i < 2; i++) {
            int f = tid + i*256;
            int r = f >> 3, ch = f & 7;
            uint32_t off = (uint32_t)(r*PW + ch*4)*4u;
            cpa16(kB + off, g_Kf + base + (size_t)(s0 + r)*DK + ch*8);
            cpa16(vB + off, g_Vf + vbase + (size_t)r*SEQ + s0 + ch*8);
        }
    };

    // prologue: Q (256 rows x 8 granules = 2048, 8/thread) + tile0, tile1
#pragma unroll
    for (int i = 0; i < 8; i++) {
        int f = tid + i*256;
        int r = f >> 3, ch = f & 7;
        cpa16(sbase + (uint32_t)(r*PW + ch*4)*4u,
              g_Qf + base + (size_t)(q0 + r)*DK + ch*8);
    }
    stageKV(0, 0);
    CP_COMMIT();
    stageKV(1, 1);
    CP_COMMIT();

    float of2[2][8][4];
    float mm[2][2], ll[2][2];
#pragma unroll
    for (int hh = 0; hh < 2; hh++) {
        mm[hh][0] = -1e30f; mm[hh][1] = -1e30f;
        ll[hh][0] = 0.f;    ll[hh][1] = 0.f;
#pragma unroll
        for (int dt = 0; dt < 8; dt++)
#pragma unroll
            for (int j = 0; j < 4; j++) of2[hh][dt][j] = 0.f;
    }

    const int NT = SEQ/64;
    int cb = 0;    // compute buffer = t % 3
    for (int t = 0; t < NT; t++) {
        CP_WAIT1();          // tile t's group complete (t+1 may still fly)
        __syncthreads();     // tile t visible; buffer (t-1)%3 reader-free

        // prefetch tile t+2 immediately into the freed buffer
        int nb = cb + 2; if (nb >= 3) nb -= 3;
        if (t + 2 < NT) stageKV(t + 2, nb);
        CP_COMMIT();         // uniform depth (possibly empty)

        uint32_t kA = sbase + (uint32_t)(AQ_SZ + cb*AK_SZ)*4u + bOffW*4u;
        uint32_t vA = sbase + (uint32_t)(AQ_SZ + (3 + cb)*AK_SZ)*4u + bOffW*4u;

#pragma unroll
        for (int hh = 0; hh < 2; hh++) {
            uint32_t qA = sbase + qOff[hh]*4u;

            // S = Q . K^T
            float sacc[8][4];
#pragma unroll
            for (int nt = 0; nt < 8; nt++)
#pragma unroll
                for (int j = 0; j < 4; j++) sacc[nt][j] = 0.f;
#pragma unroll
            for (int ks = 0; ks < 4; ks++) {
                uint32_t off = (uint32_t)(ks*8)*4u;
                uint32_t qf[4];
                ldsm4(qf, qA + off);
#pragma unroll
                for (int p = 0; p < 4; p++) {
                    uint32_t kb[4];
                    ldsm4(kb, kA + (uint32_t)(p*16*PW)*4u + off);
                    mma_fp16(sacc[2*p],   qf, kb[0], kb[1]);
                    mma_fp16(sacc[2*p+1], qf, kb[2], kb[3]);
                }
            }

            // online softmax (log2 domain; Q prescaled)
            float tm0 = -1e30f, tm1 = -1e30f;
#pragma unroll
            for (int nt = 0; nt < 8; nt++) {
                tm0 = fmaxf(tm0, fmaxf(sacc[nt][0], sacc[nt][1]));
                tm1 = fmaxf(tm1, fmaxf(sacc[nt][2], sacc[nt][3]));
            }
            tm0 = fmaxf(tm0, __shfl_xor_sync(0xffffffffu, tm0, 1));
            tm0 = fmaxf(tm0, __shfl_xor_sync(0xffffffffu, tm0, 2));
            tm1 = fmaxf(tm1, __shfl_xor_sync(0xffffffffu, tm1, 1));
            tm1 = fmaxf(tm1, __shfl_xor_sync(0xffffffffu, tm1, 2));

            float mn0 = fmaxf(mm[hh][0], tm0), mn1 = fmaxf(mm[hh][1], tm1);
            float a0 = ex2f(mm[hh][0] - mn0), a1 = ex2f(mm[hh][1] - mn1);
            mm[hh][0] = mn0; mm[hh][1] = mn1;

            // P via f16x2 ex2, directly in pa register layout
            uint32_t pp[16];
            float rs0 = 0.f, rs1 = 0.f;
#pragma unroll
            for (int nt = 0; nt < 8; nt++) {
                pp[2*nt]   = h2ex2(packh2(sacc[nt][0] - mn0, sacc[nt][1] - mn0));
                pp[2*nt+1] = h2ex2(packh2(sacc[nt][2] - mn1, sacc[nt][3] - mn1));
                float2 u0 = h2unpack(pp[2*nt]);
                float2 u1 = h2unpack(pp[2*nt+1]);
                rs0 += u0.x + u0.y;
                rs1 += u1.x + u1.y;
            }
            rs0 += __shfl_xor_sync(0xffffffffu, rs0, 1);
            rs0 += __shfl_xor_sync(0xffffffffu, rs0, 2);
            rs1 += __shfl_xor_sync(0xffffffffu, rs1, 1);
            rs1 += __shfl_xor_sync(0xffffffffu, rs1, 2);
            ll[hh][0] = ll[hh][0] * a0 + rs0;
            ll[hh][1] = ll[hh][1] * a1 + rs1;
#pragma unroll
            for (int dt = 0; dt < 8; dt++) {
                of2[hh][dt][0] *= a0; of2[hh][dt][1] *= a0;
                of2[hh][dt][2] *= a1; of2[hh][dt][3] *= a1;
            }

            // O += P . V
#pragma unroll
            for (int ks = 0; ks < 4; ks++) {
                uint32_t off = (uint32_t)(ks*8)*4u;
#pragma unroll
                for (int p = 0; p < 4; p++) {
                    uint32_t vb[4];
                    ldsm4(vb, vA + (uint32_t)(p*16*PW)*4u + off);
                    mma_fp16(of2[hh][2*p],   &pp[4*ks], vb[0], vb[1]);
                    mma_fp16(of2[hh][2*p+1], &pp[4*ks], vb[2], vb[3]);
                }
            }
        }

        cb = (cb == 2) ? 0 : cb + 1;
    }

    // epilogue: normalize -> fp16 ctx, [b, s, h, d] concat layout
    const int b = bh >> 4, h = bh & 15;
#pragma unroll
    for (int hh = 0; hh < 2; hh++) {
        float inv0 = 1.0f / ll[hh][0], inv1 = 1.0f / ll[hh][1];
        const int sg0 = q0 + hh*128 + w*16 + g, sg1 = sg0 + 8;
#pragma unroll
        for (int dt = 0; dt < 8; dt++) {
            int dcol = dt*8 + 2*tg;
            size_t i0 = ((size_t)(b*SEQ + sg0) * NH + h) * DK + dcol;
            size_t i1 = ((size_t)(b*SEQ + sg1) * NH + h) * DK + dcol;
            *(uint32_t*)&g_Cf[i0] = packh2(of2[hh][dt][0]*inv0, of2[hh][dt][1]*inv0);
            *(uint32_t*)&g_Cf[i1] = packh2(of2[hh][dt][2]*inv1, of2[hh][dt][3]*inv1);
        }
    }
}

// ---------------------------------------------------------------------------
extern "C" void kernel_launch(void* const* d_in, const int* in_sizes, int n_in,
                              void* d_out, int out_size)
{
    const float* Xq = (const float*)d_in[0];
    const float* Xk = (const float*)d_in[1];
    const float* Xv = (const float*)d_in[2];
    const float* Wq = (const float*)d_in[3];
    const float* bq = (const float*)d_in[4];
    const float* Wk = (const float*)d_in[5];
    const float* bk = (const float*)d_in[6];
    const float* Wv = (const float*)d_in[7];
    const float* bv = (const float*)d_in[8];
    const float* Wo = (const float*)d_in[9];
    const float* bo = (const float*)d_in[10];
    float* out = (float*)d_out;

    cudaFuncSetAttribute(gemm_fp16,
                         cudaFuncAttributeMaxDynamicSharedMemorySize,
                         GEMM_SMEM_BYTES);
    cudaFuncSetAttribute(attn_fp16,
                         cudaFuncAttributeMaxDynamicSharedMemorySize,
                         ATTN_SMEM_BYTES);

    prep<<<dim3(1024, 1, 7), 256>>>(Wq, Wk, Wv, Wo, Xq, Xk, Xv);

    dim3 gq(DM/128, MROWS/128, 3);   // fused QKV: 8 x 32 x 3 = 768 blocks
    gemm_fp16<<<gq, 256, GEMM_SMEM_BYTES>>>(1, bq, bk, bv, nullptr);

    dim3 ga(SEQ/256, BATCH*NH);      // 8 x 32 = 256 blocks (single wave)
    attn_fp16<<<ga, 256, ATTN_SMEM_BYTES>>>();

    dim3 gp(DM/128, MROWS/128, 1);   // out projection: 256 blocks
    gemm_fp16<<<gp, 256, GEMM_SMEM_BYTES>>>(0, bo, bo, bo, out);
}

// round 16
// speedup vs baseline: 1.1281x; 1.1281x over previous
#include <cuda_runtime.h>
#include <cuda_fp16.h>
#include <cstdint>

#define DM   1024
#define NH   16
#define DK   64
#define BATCH 2
#define SEQ  2048
#define MROWS (BATCH*SEQ)   // 4096
#define NW   (DM*DM)
#define NX   (MROWS*DM)
#define NHD  (BATCH*NH*SEQ*DK)

// Scratch (sanctioned __device__ globals)
__device__ __half g_Wf[4*NW];    // fp16 weights (Wq,Wk,Wv,Wo)
__device__ __half g_Xf[3*NX];    // fp16 inputs
__device__ __half g_Cf[NX];      // fp16 ctx [b,s,h*d]
__device__ __half g_Qf[NHD];     // fp16 Q (prescaled) [b,h,s,d]
__device__ __half g_Kf[NHD];     // fp16 K [b,h,s,d]
__device__ __half g_Vf[NHD];     // fp16 V TRANSPOSED [b,h,d,s]

// ---------------------------------------------------------------------------
// helpers
// ---------------------------------------------------------------------------
__device__ __forceinline__ float ex2f(float x) {
    float y;
    asm("ex2.approx.f32 %0, %1;" : "=f"(y) : "f"(x));
    return y;
}
__device__ __forceinline__ uint32_t h2ex2(uint32_t x) {
    uint32_t y;
    asm("ex2.approx.f16x2 %0, %1;" : "=r"(y) : "r"(x));
    return y;
}
__device__ __forceinline__ uint32_t packh2(float lo, float hi) {
    uint32_t u;
    asm("cvt.rn.f16x2.f32 %0, %1, %2;" : "=r"(u) : "f"(hi), "f"(lo));
    return u;
}
__device__ __forceinline__ float2 h2unpack(uint32_t u) {
    __half2 h = *reinterpret_cast<__half2*>(&u);
    return __half22float2(h);
}
__device__ __forceinline__ void mma_fp16(float* c, const uint32_t* a,
                                         uint32_t b0, uint32_t b1) {
    asm volatile(
        "mma.sync.aligned.m16n8k16.row.col.f32.f16.f16.f32 "
        "{%0,%1,%2,%3},{%4,%5,%6,%7},{%8,%9},{%0,%1,%2,%3};"
        : "+f"(c[0]), "+f"(c[1]), "+f"(c[2]), "+f"(c[3])
        : "r"(a[0]), "r"(a[1]), "r"(a[2]), "r"(a[3]), "r"(b0), "r"(b1));
}
__device__ __forceinline__ void ldsm4(uint32_t* r, uint32_t addr) {
    asm volatile("ldmatrix.sync.aligned.m8n8.x4.shared.b16 {%0,%1,%2,%3}, [%4];"
        : "=r"(r[0]), "=r"(r[1]), "=r"(r[2]), "=r"(r[3]) : "r"(addr));
}
__device__ __forceinline__ void cpa16(uint32_t dst, const void* src) {
    asm volatile("cp.async.cg.shared.global [%0], [%1], 16;\n"
                 :: "r"(dst), "l"(src));
}
#define CP_COMMIT() asm volatile("cp.async.commit_group;\n" ::: "memory")
#define CP_WAIT1()  asm volatile("cp.async.wait_group 1;\n" ::: "memory")
#define CP_WAIT2()  asm volatile("cp.async.wait_group 2;\n" ::: "memory")

// ---------------------------------------------------------------------------
// prep: plain fp16 conversion. z 0-3 weights, z 4-6 inputs.
// ---------------------------------------------------------------------------
__global__ __launch_bounds__(256)
void prep(const float* __restrict__ Wq, const float* __restrict__ Wk,
          const float* __restrict__ Wv, const float* __restrict__ Wo,
          const float* __restrict__ Xq, const float* __restrict__ Xk,
          const float* __restrict__ Xv)
{
    const int z = blockIdx.z;
    const float* src = (z==0)?Wq:(z==1)?Wk:(z==2)?Wv:(z==3)?Wo:
                       (z==4)?Xq:(z==5)?Xk:Xv;
    __half* dst = (z < 4) ? (g_Wf + (size_t)z*NW) : (g_Xf + (size_t)(z-4)*NX);
    const int n4 = ((z < 4) ? NW : NX) >> 2;
    const int stride = gridDim.x * blockDim.x;
    for (int i = blockIdx.x*blockDim.x + threadIdx.x; i < n4; i += stride) {
        float4 v = ((const float4*)src)[i];
        uint2 u;
        u.x = packh2(v.x, v.y);
        u.y = packh2(v.z, v.w);
        *(uint2*)&dst[(size_t)i*4] = u;
    }
}

// ---------------------------------------------------------------------------
// GEMM on mma.sync fp16 m16n8k16 + ldmatrix, 4-stage cp.async pipeline,
// prefetch issued right after the barrier (target (kc-1)%4 reader-free).
// Block 128m x 128n, K-chunk 32, 8 warps as 4m x 2n (warp 32x64).
// ---------------------------------------------------------------------------
#define PW2 20
#define S_A2 (128*PW2)                 // 2560 words A
#define STG2 (2*S_A2)                  // 5120 words per stage (A + W)
#define GEMM_SMEM_BYTES (4*STG2*4)     // 81920

__global__ __launch_bounds__(256, 2)
void gemm_fp16(int mode, const float* __restrict__ b0p,
               const float* __restrict__ b1p, const float* __restrict__ b2p,
               float* __restrict__ outp)
{
    extern __shared__ uint32_t gsm[];

    const int z = blockIdx.z;
    const __half* Af = mode ? (g_Xf + (size_t)z*NX) : g_Cf;
    const int wsel = mode ? z : 3;
    const __half* WG = g_Wf + (size_t)wsel*NW;
    const float* bias = mode ? ((z==0)?b0p:(z==1)?b1p:b2p) : b0p;

    const int m0 = blockIdx.y * 128;
    const int n0 = blockIdx.x * 128;
    const int tid = threadIdx.x;
    const int w = tid >> 5;
    const int lane = tid & 31;
    const int g = lane >> 2, tg = lane & 3;
    const int wm = w & 3;
    const int wn = w >> 2;

    const uint32_t sbase = (uint32_t)__cvta_generic_to_shared(gsm);

    const uint32_t aOffW = (uint32_t)((wm*32 + (lane&7) + ((lane>>3)&1)*8)*PW2
                                      + (lane>>4)*4);
    const uint32_t wOffW = (uint32_t)((wn*64 + ((lane>>4)&1)*8 + (lane&7))*PW2
                                      + ((lane>>3)&1)*4);

    auto stage = [&](int kc, int s) {
        int k0 = kc * 32;
        uint32_t bb = sbase + (uint32_t)(s * STG2) * 4u;
#pragma unroll
        for (int i = 0; i < 2; i++) {
            int f = tid + i*256;
            int r = f >> 2, ch = f & 3;
            cpa16(bb + (uint32_t)(r*PW2 + ch*4)*4u,
                  Af + (size_t)(m0 + r)*DM + k0 + ch*8);
        }
#pragma unroll
        for (int i = 0; i < 2; i++) {
            int f = tid + i*256;
            int r = f >> 2, ch = f & 3;
            cpa16(bb + S_A2*4u + (uint32_t)(r*PW2 + ch*4)*4u,
                  WG + (size_t)(n0 + r)*DM + k0 + ch*8);
        }
    };

    float acc[2][8][4];
#pragma unroll
    for (int mi = 0; mi < 2; mi++)
#pragma unroll
        for (int nt = 0; nt < 8; nt++)
#pragma unroll
            for (int j = 0; j < 4; j++) acc[mi][nt][j] = 0.f;

    stage(0, 0); CP_COMMIT();
    stage(1, 1); CP_COMMIT();
    stage(2, 2); CP_COMMIT();

    const int NCH = DM/32;   // 32 chunks
    for (int kc = 0; kc < NCH; kc++) {
        CP_WAIT2();          // chunk kc complete (kc+1, kc+2 may still fly)
        __syncthreads();     // visible; buffer (kc-1)%4 reader-free

        // prefetch chunk kc+3 immediately (target buffer freed last iter)
        if (kc + 3 < NCH) stage(kc + 3, (kc + 3) & 3);
        CP_COMMIT();         // uniform depth (possibly empty)

        uint32_t bb = sbase + (uint32_t)((kc & 3) * STG2) * 4u;
        uint32_t aA = bb + aOffW*4u;
        uint32_t wB = bb + S_A2*4u + wOffW*4u;

#pragma unroll
        for (int ks = 0; ks < 2; ks++) {
            uint32_t off = (uint32_t)(ks*8)*4u;
            uint32_t af[2][4];
            ldsm4(af[0], aA + off);
            ldsm4(af[1], aA + (uint32_t)(16*PW2)*4u + off);
#pragma unroll
            for (int p = 0; p < 4; p++) {
                uint32_t wb[4];
                ldsm4(wb, wB + (uint32_t)(p*16*PW2)*4u + off);
#pragma unroll
                for (int q = 0; q < 2; q++) {
                    int nt = p*2 + q;
#pragma unroll
                    for (int mi = 0; mi < 2; mi++)
                        mma_fp16(acc[mi][nt], af[mi], wb[q*2], wb[q*2+1]);
                }
            }
        }
    }

    // epilogue
    const float QSCALE = 0.125f * 1.4426950408889634f;
#pragma unroll
    for (int nt = 0; nt < 8; nt++) {
        int ncl = wn*64 + nt*8 + 2*tg;
        int gn = n0 + ncl;
        float bb0 = bias[gn], bb1 = bias[gn + 1];
#pragma unroll
        for (int mi = 0; mi < 2; mi++) {
            int mA = m0 + wm*32 + mi*16 + g;
            int mB = mA + 8;
            float x0 = acc[mi][nt][0] + bb0, x1 = acc[mi][nt][1] + bb1;
            float y0 = acc[mi][nt][2] + bb0, y1 = acc[mi][nt][3] + bb1;
            if (mode) {
                int bA = mA >> 11, sA = mA & (SEQ-1);
                int sB = sA + 8;
                int h = gn >> 6, d = gn & 63;
                if (z == 2) {
                    size_t vb = ((size_t)(bA*NH + h)) * DK;
                    g_Vf[(vb + d  )*SEQ + sA] = __float2half_rn(x0);
                    g_Vf[(vb + d+1)*SEQ + sA] = __float2half_rn(x1);
                    g_Vf[(vb + d  )*SEQ + sB] = __float2half_rn(y0);
                    g_Vf[(vb + d+1)*SEQ + sB] = __float2half_rn(y1);
                } else {
                    __half* dst = (z == 0) ? g_Qf : g_Kf;
                    float sc = (z == 0) ? QSCALE : 1.0f;
                    size_t oA = (((size_t)(bA*NH + h)) * SEQ + sA) * DK + d;
                    size_t oB = (((size_t)(bA*NH + h)) * SEQ + sB) * DK + d;
                    *(uint32_t*)&dst[oA] = packh2(x0*sc, x1*sc);
                    *(uint32_t*)&dst[oB] = packh2(y0*sc, y1*sc);
                }
            } else {
                *(float2*)&outp[(size_t)mA * DM + gn] = make_float2(x0, x1);
                *(float2*)&outp[(size_t)mB * DM + gn] = make_float2(y0, y1);
            }
        }
    }
}

// ---------------------------------------------------------------------------
// Flash attention, fp16 m16n8k16 + ldmatrix (R13 champion structure):
//  - q-tile 128, triple-buffered K/V, ONE __syncthreads per tile
//  - prefetch issued right after the barrier (freed buffer reader-free)
//  - P via ex2.approx.f16x2 directly in pa register layout
// smem: Qs 128x36 | Ks[3] 64x36 | Vs[3] 64x36 = 73728 B; 2 blocks/SM.
// ---------------------------------------------------------------------------
#define PW 36
#define AQ_SZ (128*PW)   // 4608 words
#define AK_SZ (64*PW)    // 2304 words
#define ATTN_SMEM_BYTES ((AQ_SZ + 6*AK_SZ)*4)   // 73728

__global__ __launch_bounds__(256, 2)
void attn_fp16()
{
    extern __shared__ uint32_t sm[];

    const int bh = blockIdx.y;
    const int q0 = blockIdx.x * 128;
    const size_t base = (size_t)bh * SEQ * DK;     // [b,h,s,d] Q/K
    const size_t vbase = (size_t)bh * DK * SEQ;    // [b,h,d,s] V
    const int tid = threadIdx.x;
    const int w = tid >> 5;
    const int lane = tid & 31;
    const int g = lane >> 2, tg = lane & 3;

    const uint32_t sbase = (uint32_t)__cvta_generic_to_shared(sm);

    const uint32_t qOffW = (uint32_t)((w*16 + (lane&7) + ((lane>>3)&1)*8)*PW
                                      + (lane>>4)*4);
    const uint32_t bOffW = (uint32_t)((((lane>>4)&1)*8 + (lane&7))*PW
                                      + ((lane>>3)&1)*4);

    auto stageKV = [&](int t, int b) {
        int s0 = t * 64;
        uint32_t kB = sbase + (uint32_t)(AQ_SZ + b*AK_SZ)*4u;
        uint32_t vB = sbase + (uint32_t)(AQ_SZ + (3 + b)*AK_SZ)*4u;
#pragma unroll
        for (int i = 0; i < 2; i++) {
            int f = tid + i*256;
            int r = f >> 3, ch = f & 7;
            uint32_t off = (uint32_t)(r*PW + ch*4)*4u;
            cpa16(kB + off, g_Kf + base + (size_t)(s0 + r)*DK + ch*8);
            cpa16(vB + off, g_Vf + vbase + (size_t)r*SEQ + s0 + ch*8);
        }
    };

    // prologue: Q + tile0 (group 0), tile1 (group 1)
#pragma unroll
    for (int i = 0; i < 4; i++) {
        int f = tid + i*256;
        int r = f >> 3, ch = f & 7;
        cpa16(sbase + (uint32_t)(r*PW + ch*4)*4u,
              g_Qf + base + (size_t)(q0 + r)*DK + ch*8);
    }
    stageKV(0, 0);
    CP_COMMIT();
    stageKV(1, 1);
    CP_COMMIT();

    float of[8][4];
#pragma unroll
    for (int dt = 0; dt < 8; dt++)
#pragma unroll
        for (int j = 0; j < 4; j++) of[dt][j] = 0.f;
    float m0 = -1e30f, m1 = -1e30f, l0 = 0.f, l1 = 0.f;

    const int NT = SEQ/64;
    int cb = 0;    // compute buffer = t % 3
    for (int t = 0; t < NT; t++) {
        CP_WAIT1();          // tile t's group complete (t+1 may still fly)
        __syncthreads();     // tile t visible; buffer (t-1)%3 reader-free

        // prefetch tile t+2 immediately into the freed buffer
        int nb = cb + 2; if (nb >= 3) nb -= 3;
        if (t + 2 < NT) stageKV(t + 2, nb);
        CP_COMMIT();         // uniform depth (possibly empty)

        uint32_t qA = sbase + qOffW*4u;
        uint32_t kA = sbase + (uint32_t)(AQ_SZ + cb*AK_SZ)*4u + bOffW*4u;
        uint32_t vA = sbase + (uint32_t)(AQ_SZ + (3 + cb)*AK_SZ)*4u + bOffW*4u;

        // S = Q . K^T
        float sacc[8][4];
#pragma unroll
        for (int nt = 0; nt < 8; nt++)
#pragma unroll
            for (int j = 0; j < 4; j++) sacc[nt][j] = 0.f;
#pragma unroll
        for (int ks = 0; ks < 4; ks++) {
            uint32_t off = (uint32_t)(ks*8)*4u;
            uint32_t qf[4];
            ldsm4(qf, qA + off);
#pragma unroll
            for (int p = 0; p < 4; p++) {
                uint32_t kb[4];
                ldsm4(kb, kA + (uint32_t)(p*16*PW)*4u + off);
                mma_fp16(sacc[2*p],   qf, kb[0], kb[1]);
                mma_fp16(sacc[2*p+1], qf, kb[2], kb[3]);
            }
        }

        // online softmax (log2 domain; Q prescaled)
        float tm0 = -1e30f, tm1 = -1e30f;
#pragma unroll
        for (int nt = 0; nt < 8; nt++) {
            tm0 = fmaxf(tm0, fmaxf(sacc[nt][0], sacc[nt][1]));
            tm1 = fmaxf(tm1, fmaxf(sacc[nt][2], sacc[nt][3]));
        }
        tm0 = fmaxf(tm0, __shfl_xor_sync(0xffffffffu, tm0, 1));
        tm0 = fmaxf(tm0, __shfl_xor_sync(0xffffffffu, tm0, 2));
        tm1 = fmaxf(tm1, __shfl_xor_sync(0xffffffffu, tm1, 1));
        tm1 = fmaxf(tm1, __shfl_xor_sync(0xffffffffu, tm1, 2));

        float mn0 = fmaxf(m0, tm0), mn1 = fmaxf(m1, tm1);
        float a0 = ex2f(m0 - mn0), a1 = ex2f(m1 - mn1);
        m0 = mn0; m1 = mn1;

        // P via f16x2 ex2, directly in pa register layout
        uint32_t pp[16];
        float rs0 = 0.f, rs1 = 0.f;
#pragma unroll
        for (int nt = 0; nt < 8; nt++) {
            pp[2*nt]   = h2ex2(packh2(sacc[nt][0] - mn0, sacc[nt][1] - mn0));
            pp[2*nt+1] = h2ex2(packh2(sacc[nt][2] - mn1, sacc[nt][3] - mn1));
            float2 u0 = h2unpack(pp[2*nt]);
            float2 u1 = h2unpack(pp[2*nt+1]);
            rs0 += u0.x + u0.y;
            rs1 += u1.x + u1.y;
        }
        rs0 += __shfl_xor_sync(0xffffffffu, rs0, 1);
        rs0 += __shfl_xor_sync(0xffffffffu, rs0, 2);
        rs1 += __shfl_xor_sync(0xffffffffu, rs1, 1);
        rs1 += __shfl_xor_sync(0xffffffffu, rs1, 2);
        l0 = l0 * a0 + rs0;
        l1 = l1 * a1 + rs1;
#pragma unroll
        for (int dt = 0; dt < 8; dt++) {
            of[dt][0] *= a0; of[dt][1] *= a0;
            of[dt][2] *= a1; of[dt][3] *= a1;
        }

        // O += P . V (pa comes straight from pp)
#pragma unroll
        for (int ks = 0; ks < 4; ks++) {
            uint32_t off = (uint32_t)(ks*8)*4u;
#pragma unroll
            for (int p = 0; p < 4; p++) {
                uint32_t vb[4];
                ldsm4(vb, vA + (uint32_t)(p*16*PW)*4u + off);
                mma_fp16(of[2*p],   &pp[4*ks], vb[0], vb[1]);
                mma_fp16(of[2*p+1], &pp[4*ks], vb[2], vb[3]);
            }
        }

        cb = (cb == 2) ? 0 : cb + 1;
    }

    // epilogue: normalize -> fp16 ctx, [b, s, h, d] concat layout
    float inv0 = 1.0f / l0, inv1 = 1.0f / l1;
    const int b = bh >> 4, h = bh & 15;
    const int sg0 = q0 + w*16 + g, sg1 = sg0 + 8;
#pragma unroll
    for (int dt = 0; dt < 8; dt++) {
        int dcol = dt*8 + 2*tg;
        size_t i0 = ((size_t)(b*SEQ + sg0) * NH + h) * DK + dcol;
        size_t i1 = ((size_t)(b*SEQ + sg1) * NH + h) * DK + dcol;
        *(uint32_t*)&g_Cf[i0] = packh2(of[dt][0]*inv0, of[dt][1]*inv0);
        *(uint32_t*)&g_Cf[i1] = packh2(of[dt][2]*inv1, of[dt][3]*inv1);
    }
}

// ---------------------------------------------------------------------------
extern "C" void kernel_launch(void* const* d_in, const int* in_sizes, int n_in,
                              void* d_out, int out_size)
{
    const float* Xq = (const float*)d_in[0];
    const float* Xk = (const float*)d_in[1];
    const float* Xv = (const float*)d_in[2];
    const float* Wq = (const float*)d_in[3];
    const float* bq = (const float*)d_in[4];
    const float* Wk = (const float*)d_in[5];
    const float* bk = (const float*)d_in[6];
    const float* Wv = (const float*)d_in[7];
    const float* bv = (const float*)d_in[8];
    const float* Wo = (const float*)d_in[9];
    const float* bo = (const float*)d_in[10];
    float* out = (float*)d_out;

    cudaFuncSetAttribute(gemm_fp16,
                         cudaFuncAttributeMaxDynamicSharedMemorySize,
                         GEMM_SMEM_BYTES);
    cudaFuncSetAttribute(attn_fp16,
                         cudaFuncAttributeMaxDynamicSharedMemorySize,
                         ATTN_SMEM_BYTES);

    prep<<<dim3(1024, 1, 7), 256>>>(Wq, Wk, Wv, Wo, Xq, Xk, Xv);

    dim3 gq(DM/128, MROWS/128, 3);   // fused QKV: 8 x 32 x 3 = 768 blocks
    gemm_fp16<<<gq, 256, GEMM_SMEM_BYTES>>>(1, bq, bk, bv, nullptr);

    dim3 ga(SEQ/128, BATCH*NH);      // 16 x 32 = 512 blocks
    attn_fp16<<<ga, 256, ATTN_SMEM_BYTES>>>();

    dim3 gp(DM/128, MROWS/128, 1);   // out projection: 256 blocks
    gemm_fp16<<<gp, 256, GEMM_SMEM_BYTES>>>(0, bo, bo, bo, out);
}

// round 17
// speedup vs baseline: 1.2237x; 1.0847x over previous
#include <cuda_runtime.h>
#include <cuda_fp16.h>
#include <cstdint>

#define DM   1024
#define NH   16
#define DK   64
#define BATCH 2
#define SEQ  2048
#define MROWS (BATCH*SEQ)   // 4096
#define NW   (DM*DM)
#define NX   (MROWS*DM)
#define NHD  (BATCH*NH*SEQ*DK)

// Scratch (sanctioned __device__ globals)
__device__ __half g_Wf[4*NW];    // fp16 weights (Wq,Wk,Wv,Wo)
__device__ __half g_Xf[3*NX];    // fp16 inputs
__device__ __half g_Cf[NX];      // fp16 ctx [b,s,h*d]
__device__ __half g_Qf[NHD];     // fp16 Q (prescaled) [b,h,s,d]
__device__ __half g_Kf[NHD];     // fp16 K [b,h,s,d]
__device__ __half g_Vf[NHD];     // fp16 V TRANSPOSED [b,h,d,s]

// ---------------------------------------------------------------------------
// helpers
// ---------------------------------------------------------------------------
__device__ __forceinline__ float ex2f(float x) {
    float y;
    asm("ex2.approx.f32 %0, %1;" : "=f"(y) : "f"(x));
    return y;
}
__device__ __forceinline__ uint32_t h2ex2(uint32_t x) {
    uint32_t y;
    asm("ex2.approx.f16x2 %0, %1;" : "=r"(y) : "r"(x));
    return y;
}
__device__ __forceinline__ uint32_t packh2(float lo, float hi) {
    uint32_t u;
    asm("cvt.rn.f16x2.f32 %0, %1, %2;" : "=r"(u) : "f"(hi), "f"(lo));
    return u;
}
__device__ __forceinline__ float2 h2unpack(uint32_t u) {
    __half2 h = *reinterpret_cast<__half2*>(&u);
    return __half22float2(h);
}
__device__ __forceinline__ void mma_fp16(float* c, const uint32_t* a,
                                         uint32_t b0, uint32_t b1) {
    asm volatile(
        "mma.sync.aligned.m16n8k16.row.col.f32.f16.f16.f32 "
        "{%0,%1,%2,%3},{%4,%5,%6,%7},{%8,%9},{%0,%1,%2,%3};"
        : "+f"(c[0]), "+f"(c[1]), "+f"(c[2]), "+f"(c[3])
        : "r"(a[0]), "r"(a[1]), "r"(a[2]), "r"(a[3]), "r"(b0), "r"(b1));
}
__device__ __forceinline__ void ldsm4(uint32_t* r, uint32_t addr) {
    asm volatile("ldmatrix.sync.aligned.m8n8.x4.shared.b16 {%0,%1,%2,%3}, [%4];"
        : "=r"(r[0]), "=r"(r[1]), "=r"(r[2]), "=r"(r[3]) : "r"(addr));
}
__device__ __forceinline__ void cpa16(uint32_t dst, const void* src) {
    asm volatile("cp.async.cg.shared.global [%0], [%1], 16;\n"
                 :: "r"(dst), "l"(src));
}
#define CP_COMMIT() asm volatile("cp.async.commit_group;\n" ::: "memory")
#define CP_WAIT1()  asm volatile("cp.async.wait_group 1;\n" ::: "memory")

// ---------------------------------------------------------------------------
// prep: plain fp16 conversion. z 0-3 weights, z 4-6 inputs.
// ---------------------------------------------------------------------------
__global__ __launch_bounds__(256)
void prep(const float* __restrict__ Wq, const float* __restrict__ Wk,
          const float* __restrict__ Wv, const float* __restrict__ Wo,
          const float* __restrict__ Xq, const float* __restrict__ Xk,
          const float* __restrict__ Xv)
{
    const int z = blockIdx.z;
    const float* src = (z==0)?Wq:(z==1)?Wk:(z==2)?Wv:(z==3)?Wo:
                       (z==4)?Xq:(z==5)?Xk:Xv;
    __half* dst = (z < 4) ? (g_Wf + (size_t)z*NW) : (g_Xf + (size_t)(z-4)*NX);
    const int n4 = ((z < 4) ? NW : NX) >> 2;
    const int stride = gridDim.x * blockDim.x;
    for (int i = blockIdx.x*blockDim.x + threadIdx.x; i < n4; i += stride) {
        float4 v = ((const float4*)src)[i];
        uint2 u;
        u.x = packh2(v.x, v.y);
        u.y = packh2(v.z, v.w);
        *(uint2*)&dst[(size_t)i*4] = u;
    }
}

// ---------------------------------------------------------------------------
// GEMM on mma.sync fp16 m16n8k16 + ldmatrix, 3-stage cp.async pipeline,
// K-chunk 64 (4 k16 slabs) -> 16 chunks, ONE __syncthreads per chunk
// (stage target (kc+2)%3 has no live readers past the iter-kc barrier).
// Stage-after-compute ordering (proven R13 placement). Prefetch distance 2.
// Block 128m x 128n, 8 warps as 4m x 2n (warp 32x64). Pitch 36 words
// (R10-proven conflict-free LDSM layout).
// mode=1: z picks Xq->Qf(prescaled), Xk->Kf, Xv->Vf(transposed [b,h,d,s])
// mode=0: (ctx, Wo) -> out fp32 + bias
// ---------------------------------------------------------------------------
#define PW3 36
#define SA3 (128*PW3)                  // 4608 words per operand
#define STG3 (2*SA3)                   // 9216 words per stage (A + W)
#define GEMM_SMEM_BYTES (3*STG3*4)     // 110592

__global__ __launch_bounds__(256, 2)
void gemm_fp16(int mode, const float* __restrict__ b0p,
               const float* __restrict__ b1p, const float* __restrict__ b2p,
               float* __restrict__ outp)
{
    extern __shared__ uint32_t gsm[];

    const int z = blockIdx.z;
    const __half* Af = mode ? (g_Xf + (size_t)z*NX) : g_Cf;
    const int wsel = mode ? z : 3;
    const __half* WG = g_Wf + (size_t)wsel*NW;
    const float* bias = mode ? ((z==0)?b0p:(z==1)?b1p:b2p) : b0p;

    const int m0 = blockIdx.y * 128;
    const int n0 = blockIdx.x * 128;
    const int tid = threadIdx.x;
    const int w = tid >> 5;
    const int lane = tid & 31;
    const int g = lane >> 2, tg = lane & 3;
    const int wm = w & 3;              // 4 m-groups of 32 rows
    const int wn = w >> 2;             // 2 n-groups of 64 cols

    const uint32_t sbase = (uint32_t)__cvta_generic_to_shared(gsm);

    // LDSM lane addressing (words within stage)
    const uint32_t aOffW = (uint32_t)((wm*32 + (lane&7) + ((lane>>3)&1)*8)*PW3
                                      + (lane>>4)*4);
    const uint32_t wOffW = (uint32_t)((wn*64 + ((lane>>4)&1)*8 + (lane&7))*PW3
                                      + ((lane>>3)&1)*4);

    // stage chunk kc (k-offset kc*64 fp16) into stage s
    auto stage = [&](int kc, int s) {
        int k0 = kc * 64;
        uint32_t bb = sbase + (uint32_t)(s * STG3) * 4u;
        // A: 128 rows x 8 granules = 1024, 4/thread
#pragma unroll
        for (int i = 0; i < 4; i++) {
            int f = tid + i*256;
            int r = f >> 3, ch = f & 7;
            cpa16(bb + (uint32_t)(r*PW3 + ch*4)*4u,
                  Af + (size_t)(m0 + r)*DM + k0 + ch*8);
        }
        // W: 128 rows x 8 granules = 1024, 4/thread
#pragma unroll
        for (int i = 0; i < 4; i++) {
            int f = tid + i*256;
            int r = f >> 3, ch = f & 7;
            cpa16(bb + SA3*4u + (uint32_t)(r*PW3 + ch*4)*4u,
                  WG + (size_t)(n0 + r)*DM + k0 + ch*8);
        }
    };

    float acc[2][8][4];
#pragma unroll
    for (int mi = 0; mi < 2; mi++)
#pragma unroll
        for (int nt = 0; nt < 8; nt++)
#pragma unroll
            for (int j = 0; j < 4; j++) acc[mi][nt][j] = 0.f;

    stage(0, 0); CP_COMMIT();
    stage(1, 1); CP_COMMIT();

    const int NCH = DM/64;   // 16 chunks
    int sb = 0;              // stage index of chunk kc
    for (int kc = 0; kc < NCH; kc++) {
        CP_WAIT1();          // chunk kc complete (kc+1 may still fly)
        __syncthreads();     // visible; buffer (kc-1)%3 reader-free

        uint32_t bb = sbase + (uint32_t)(sb * STG3) * 4u;
        uint32_t aA = bb + aOffW*4u;
        uint32_t wB = bb + SA3*4u + wOffW*4u;

#pragma unroll
        for (int ks = 0; ks < 4; ks++) {
            uint32_t off = (uint32_t)(ks*8)*4u;
            uint32_t af[2][4];
            ldsm4(af[0], aA + off);
            ldsm4(af[1], aA + (uint32_t)(16*PW3)*4u + off);
#pragma unroll
            for (int p = 0; p < 4; p++) {
                uint32_t wb[4];
                ldsm4(wb, wB + (uint32_t)(p*16*PW3)*4u + off);
#pragma unroll
                for (int q = 0; q < 2; q++) {
                    int nt = p*2 + q;
#pragma unroll
                    for (int mi = 0; mi < 2; mi++)
                        mma_fp16(acc[mi][nt], af[mi], wb[q*2], wb[q*2+1]);
                }
            }
        }

        // stage-after-compute (R13-proven placement): chunk kc+2 into the
        // buffer freed before this iteration's barrier
        int s2 = sb + 2; if (s2 >= 3) s2 -= 3;
        if (kc + 2 < NCH) stage(kc + 2, s2);
        CP_COMMIT();         // uniform depth (possibly empty)
        sb = (sb == 2) ? 0 : sb + 1;
    }

    // epilogue
    const float QSCALE = 0.125f * 1.4426950408889634f;
#pragma unroll
    for (int nt = 0; nt < 8; nt++) {
        int ncl = wn*64 + nt*8 + 2*tg;
        int gn = n0 + ncl;
        float bb0 = bias[gn], bb1 = bias[gn + 1];
#pragma unroll
        for (int mi = 0; mi < 2; mi++) {
            int mA = m0 + wm*32 + mi*16 + g;
            int mB = mA + 8;
            float x0 = acc[mi][nt][0] + bb0, x1 = acc[mi][nt][1] + bb1;
            float y0 = acc[mi][nt][2] + bb0, y1 = acc[mi][nt][3] + bb1;
            if (mode) {
                int bA = mA >> 11, sA = mA & (SEQ-1);
                int sB = sA + 8;
                int h = gn >> 6, d = gn & 63;
                if (z == 2) {
                    size_t vb = ((size_t)(bA*NH + h)) * DK;
                    g_Vf[(vb + d  )*SEQ + sA] = __float2half_rn(x0);
                    g_Vf[(vb + d+1)*SEQ + sA] = __float2half_rn(x1);
                    g_Vf[(vb + d  )*SEQ + sB] = __float2half_rn(y0);
                    g_Vf[(vb + d+1)*SEQ + sB] = __float2half_rn(y1);
                } else {
                    __half* dst = (z == 0) ? g_Qf : g_Kf;
                    float sc = (z == 0) ? QSCALE : 1.0f;
                    size_t oA = (((size_t)(bA*NH + h)) * SEQ + sA) * DK + d;
                    size_t oB = (((size_t)(bA*NH + h)) * SEQ + sB) * DK + d;
                    *(uint32_t*)&dst[oA] = packh2(x0*sc, x1*sc);
                    *(uint32_t*)&dst[oB] = packh2(y0*sc, y1*sc);
                }
            } else {
                *(float2*)&outp[(size_t)mA * DM + gn] = make_float2(x0, x1);
                *(float2*)&outp[(size_t)mB * DM + gn] = make_float2(y0, y1);
            }
        }
    }
}

// ---------------------------------------------------------------------------
// Flash attention, fp16 m16n8k16 + ldmatrix (EXACT R13 champion):
//  - q-tile 128, triple-buffered K/V, ONE __syncthreads per tile,
//    stage-after-compute placement
//  - P via ex2.approx.f16x2 directly in pa register layout
// smem: Qs 128x36 | Ks[3] 64x36 | Vs[3] 64x36 = 73728 B; 2 blocks/SM.
// ---------------------------------------------------------------------------
#define PW 36
#define AQ_SZ (128*PW)   // 4608 words
#define AK_SZ (64*PW)    // 2304 words
#define ATTN_SMEM_BYTES ((AQ_SZ + 6*AK_SZ)*4)   // 73728

__global__ __launch_bounds__(256, 2)
void attn_fp16()
{
    extern __shared__ uint32_t sm[];

    const int bh = blockIdx.y;
    const int q0 = blockIdx.x * 128;
    const size_t base = (size_t)bh * SEQ * DK;     // [b,h,s,d] Q/K
    const size_t vbase = (size_t)bh * DK * SEQ;    // [b,h,d,s] V
    const int tid = threadIdx.x;
    const int w = tid >> 5;
    const int lane = tid & 31;
    const int g = lane >> 2, tg = lane & 3;

    const uint32_t sbase = (uint32_t)__cvta_generic_to_shared(sm);

    const uint32_t qOffW = (uint32_t)((w*16 + (lane&7) + ((lane>>3)&1)*8)*PW
                                      + (lane>>4)*4);
    const uint32_t bOffW = (uint32_t)((((lane>>4)&1)*8 + (lane&7))*PW
                                      + ((lane>>3)&1)*4);

    auto stageKV = [&](int t, int b) {
        int s0 = t * 64;
        uint32_t kB = sbase + (uint32_t)(AQ_SZ + b*AK_SZ)*4u;
        uint32_t vB = sbase + (uint32_t)(AQ_SZ + (3 + b)*AK_SZ)*4u;
#pragma unroll
        for (int i = 0; i < 2; i++) {
            int f = tid + i*256;
            int r = f >> 3, ch = f & 7;
            uint32_t off = (uint32_t)(r*PW + ch*4)*4u;
            cpa16(kB + off, g_Kf + base + (size_t)(s0 + r)*DK + ch*8);
            cpa16(vB + off, g_Vf + vbase + (size_t)r*SEQ + s0 + ch*8);
        }
    };

    // prologue: Q + tile0 (group 0), tile1 (group 1)
#pragma unroll
    for (int i = 0; i < 4; i++) {
        int f = tid + i*256;
        int r = f >> 3, ch = f & 7;
        cpa16(sbase + (uint32_t)(r*PW + ch*4)*4u,
              g_Qf + base + (size_t)(q0 + r)*DK + ch*8);
    }
    stageKV(0, 0);
    CP_COMMIT();
    stageKV(1, 1);
    CP_COMMIT();

    float of[8][4];
#pragma unroll
    for (int dt = 0; dt < 8; dt++)
#pragma unroll
        for (int j = 0; j < 4; j++) of[dt][j] = 0.f;
    float m0 = -1e30f, m1 = -1e30f, l0 = 0.f, l1 = 0.f;

    const int NT = SEQ/64;
    int cb = 0;    // compute buffer = t % 3
    for (int t = 0; t < NT; t++) {
        CP_WAIT1();          // tile t's group complete (t+1 may still fly)
        __syncthreads();     // tile t visible; buffer (t-1)%3 reader-free

        uint32_t qA = sbase + qOffW*4u;
        uint32_t kA = sbase + (uint32_t)(AQ_SZ + cb*AK_SZ)*4u + bOffW*4u;
        uint32_t vA = sbase + (uint32_t)(AQ_SZ + (3 + cb)*AK_SZ)*4u + bOffW*4u;

        // S = Q . K^T
        float sacc[8][4];
#pragma unroll
        for (int nt = 0; nt < 8; nt++)
#pragma unroll
            for (int j = 0; j < 4; j++) sacc[nt][j] = 0.f;
#pragma unroll
        for (int ks = 0; ks < 4; ks++) {
            uint32_t off = (uint32_t)(ks*8)*4u;
            uint32_t qf[4];
            ldsm4(qf, qA + off);
#pragma unroll
            for (int p = 0; p < 4; p++) {
                uint32_t kb[4];
                ldsm4(kb, kA + (uint32_t)(p*16*PW)*4u + off);
                mma_fp16(sacc[2*p],   qf, kb[0], kb[1]);
                mma_fp16(sacc[2*p+1], qf, kb[2], kb[3]);
            }
        }

        // online softmax (log2 domain; Q prescaled)
        float tm0 = -1e30f, tm1 = -1e30f;
#pragma unroll
        for (int nt = 0; nt < 8; nt++) {
            tm0 = fmaxf(tm0, fmaxf(sacc[nt][0], sacc[nt][1]));
            tm1 = fmaxf(tm1, fmaxf(sacc[nt][2], sacc[nt][3]));
        }
        tm0 = fmaxf(tm0, __shfl_xor_sync(0xffffffffu, tm0, 1));
        tm0 = fmaxf(tm0, __shfl_xor_sync(0xffffffffu, tm0, 2));
        tm1 = fmaxf(tm1, __shfl_xor_sync(0xffffffffu, tm1, 1));
        tm1 = fmaxf(tm1, __shfl_xor_sync(0xffffffffu, tm1, 2));

        float mn0 = fmaxf(m0, tm0), mn1 = fmaxf(m1, tm1);
        float a0 = ex2f(m0 - mn0), a1 = ex2f(m1 - mn1);
        m0 = mn0; m1 = mn1;

        // P via f16x2 ex2, directly in pa register layout
        uint32_t pp[16];
        float rs0 = 0.f, rs1 = 0.f;
#pragma unroll
        for (int nt = 0; nt < 8; nt++) {
            pp[2*nt]   = h2ex2(packh2(sacc[nt][0] - mn0, sacc[nt][1] - mn0));
            pp[2*nt+1] = h2ex2(packh2(sacc[nt][2] - mn1, sacc[nt][3] - mn1));
            float2 u0 = h2unpack(pp[2*nt]);
            float2 u1 = h2unpack(pp[2*nt+1]);
            rs0 += u0.x + u0.y;
            rs1 += u1.x + u1.y;
        }
        rs0 += __shfl_xor_sync(0xffffffffu, rs0, 1);
        rs0 += __shfl_xor_sync(0xffffffffu, rs0, 2);
        rs1 += __shfl_xor_sync(0xffffffffu, rs1, 1);
        rs1 += __shfl_xor_sync(0xffffffffu, rs1, 2);
        l0 = l0 * a0 + rs0;
        l1 = l1 * a1 + rs1;
#pragma unroll
        for (int dt = 0; dt < 8; dt++) {
            of[dt][0] *= a0; of[dt][1] *= a0;
            of[dt][2] *= a1; of[dt][3] *= a1;
        }

        // O += P . V (pa comes straight from pp)
#pragma unroll
        for (int ks = 0; ks < 4; ks++) {
            uint32_t off = (uint32_t)(ks*8)*4u;
#pragma unroll
            for (int p = 0; p < 4; p++) {
                uint32_t vb[4];
                ldsm4(vb, vA + (uint32_t)(p*16*PW)*4u + off);
                mma_fp16(of[2*p],   &pp[4*ks], vb[0], vb[1]);
                mma_fp16(of[2*p+1], &pp[4*ks], vb[2], vb[3]);
            }
        }

        // stage-after-compute (R13 placement): tile t+2 into freed buffer
        int nb = cb + 2; if (nb >= 3) nb -= 3;
        if (t + 2 < NT) stageKV(t + 2, nb);
        CP_COMMIT();         // uniform depth (possibly empty)
        cb = (cb == 2) ? 0 : cb + 1;
    }

    // epilogue: normalize -> fp16 ctx, [b, s, h, d] concat layout
    float inv0 = 1.0f / l0, inv1 = 1.0f / l1;
    const int b = bh >> 4, h = bh & 15;
    const int sg0 = q0 + w*16 + g, sg1 = sg0 + 8;
#pragma unroll
    for (int dt = 0; dt < 8; dt++) {
        int dcol = dt*8 + 2*tg;
        size_t i0 = ((size_t)(b*SEQ + sg0) * NH + h) * DK + dcol;
        size_t i1 = ((size_t)(b*SEQ + sg1) * NH + h) * DK + dcol;
        *(uint32_t*)&g_Cf[i0] = packh2(of[dt][0]*inv0, of[dt][1]*inv0);
        *(uint32_t*)&g_Cf[i1] = packh2(of[dt][2]*inv1, of[dt][3]*inv1);
    }
}

// ---------------------------------------------------------------------------
extern "C" void kernel_launch(void* const* d_in, const int* in_sizes, int n_in,
                              void* d_out, int out_size)
{
    const float* Xq = (const float*)d_in[0];
    const float* Xk = (const float*)d_in[1];
    const float* Xv = (const float*)d_in[2];
    const float* Wq = (const float*)d_in[3];
    const float* bq = (const float*)d_in[4];
    const float* Wk = (const float*)d_in[5];
    const float* bk = (const float*)d_in[6];
    const float* Wv = (const float*)d_in[7];
    const float* bv = (const float*)d_in[8];
    const float* Wo = (const float*)d_in[9];
    const float* bo = (const float*)d_in[10];
    float* out = (float*)d_out;

    cudaFuncSetAttribute(gemm_fp16,
                         cudaFuncAttributeMaxDynamicSharedMemorySize,
                         GEMM_SMEM_BYTES);
    cudaFuncSetAttribute(attn_fp16,
                         cudaFuncAttributeMaxDynamicSharedMemorySize,
                         ATTN_SMEM_BYTES);

    prep<<<dim3(2048, 1, 7), 256>>>(Wq, Wk, Wv, Wo, Xq, Xk, Xv);

    dim3 gq(DM/128, MROWS/128, 3);   // fused QKV: 8 x 32 x 3 = 768 blocks
    gemm_fp16<<<gq, 256, GEMM_SMEM_BYTES>>>(1, bq, bk, bv, nullptr);

    dim3 ga(SEQ/128, BATCH*NH);      // 16 x 32 = 512 blocks
    attn_fp16<<<ga, 256, ATTN_SMEM_BYTES>>>();

    dim3 gp(DM/128, MROWS/128, 1);   // out projection: 256 blocks
    gemm_fp16<<<gp, 256, GEMM_SMEM_BYTES>>>(0, bo, bo, bo, out);
}